// round 1
// baseline (speedup 1.0000x reference)
#include <cuda_runtime.h>

#define BATCH 4
#define NCH   64
#define NPTS  20000
#define XSZ   512
#define YSZ   512

// -------- device scratch (allocation-free per harness rules) --------
__device__ int   g_idx[BATCH * XSZ * YSZ];                 // winner point index per pixel, -1 = empty
__device__ float g_t3[BATCH * 48 * 160 * NCH];             // c3 transposed to [b][pix][c]
__device__ float g_t4[BATCH * 24 *  80 * NCH];
__device__ float g_t5[BATCH * 12 *  40 * NCH];

// -------- 1) init winner map --------
__global__ void k_init_idx() {
    int i = blockIdx.x * blockDim.x + threadIdx.x;
    if (i < BATCH * XSZ * YSZ) g_idx[i] = -1;
}

// -------- 2) scatter point indices, last-update-wins == highest index wins --------
__global__ void k_scatter_idx(const int* __restrict__ coors,
                              const int* __restrict__ contain) {
    int i = blockIdx.x * blockDim.x + threadIdx.x;
    if (i >= BATCH * NPTS) return;
    if (contain[i] <= 0) return;
    int b  = i / NPTS;
    int p  = i - b * NPTS;
    int cx = coors[i * 3 + 1];
    int cy = coors[i * 3 + 2];
    if ((unsigned)cx >= XSZ || (unsigned)cy >= YSZ) return;
    atomicMax(&g_idx[(b * XSZ + cx) * YSZ + cy], p);
}

// -------- 3) transpose features NCHW -> [b][pix][c] (c contiguous) --------
template<int H, int W>
__global__ void k_transpose(const float* __restrict__ src, float* __restrict__ dst) {
    int i = blockIdx.x * blockDim.x + threadIdx.x;   // linear over B*H*W*C, c fastest
    if (i >= BATCH * H * W * NCH) return;
    int c   = i & (NCH - 1);
    int pix = (i >> 6) % (H * W);
    int b   = i / (H * W * NCH);
    dst[i] = src[(b * NCH + c) * (H * W) + pix];
}

// -------- 4) zero the output (HBM-write bound) --------
__global__ void k_zero(float4* __restrict__ out) {
    int i = blockIdx.x * blockDim.x + threadIdx.x;
    if (i < (BATCH * NCH * XSZ * YSZ) / 4) out[i] = make_float4(0.f, 0.f, 0.f, 0.f);
}

// -------- 5) warp-per-point bilinear sample + blend + scatter --------
template<int H, int W>
__device__ __forceinline__ void sample_map(const float* __restrict__ t,   // [pix][C] for this batch
                                           float px, float py, int lane,
                                           float d, float2& acc) {
    float x = px * (float)(W - 1);
    float y = py * (float)(H - 1);
    float x0f = floorf(x), y0f = floorf(y);
    float wx = x - x0f,    wy = y - y0f;
    int x0 = (int)x0f, y0 = (int)y0f;
    int x1 = x0 + 1,   y1 = y0 + 1;

    // validity (zeros padding) — matches reference exactly; normally all valid
    float v00 = (x0 >= 0 && x0 < W && y0 >= 0 && y0 < H) ? 1.f : 0.f;
    float v10 = (x1 >= 0 && x1 < W && y0 >= 0 && y0 < H) ? 1.f : 0.f;
    float v01 = (x0 >= 0 && x0 < W && y1 >= 0 && y1 < H) ? 1.f : 0.f;
    float v11 = (x1 >= 0 && x1 < W && y1 >= 0 && y1 < H) ? 1.f : 0.f;

    int cx0 = min(max(x0, 0), W - 1);
    int cx1 = min(max(x1, 0), W - 1);
    int cy0 = min(max(y0, 0), H - 1);
    int cy1 = min(max(y1, 0), H - 1);

    float w00 = (1.f - wx) * (1.f - wy) * v00;
    float w10 =        wx  * (1.f - wy) * v10;
    float w01 = (1.f - wx) *        wy  * v01;
    float w11 =        wx  *        wy  * v11;

    // each lane loads channels (2*lane, 2*lane+1): 32 lanes * 8B = 256B coalesced
    const float2* p00 = (const float2*)(t + (cy0 * W + cx0) * NCH) + lane;
    const float2* p10 = (const float2*)(t + (cy0 * W + cx1) * NCH) + lane;
    const float2* p01 = (const float2*)(t + (cy1 * W + cx0) * NCH) + lane;
    const float2* p11 = (const float2*)(t + (cy1 * W + cx1) * NCH) + lane;
    float2 a00 = *p00, a10 = *p10, a01 = *p01, a11 = *p11;

    acc.x += d * (w00 * a00.x + w10 * a10.x + w01 * a01.x + w11 * a11.x);
    acc.y += d * (w00 * a00.y + w10 * a10.y + w01 * a01.y + w11 * a11.y);
}

__global__ void k_points(const float* __restrict__ pnts,
                         const int*   __restrict__ coors,
                         const int*   __restrict__ contain,
                         const float* __restrict__ dyn,
                         float*       __restrict__ out) {
    int gw   = (blockIdx.x * blockDim.x + threadIdx.x) >> 5;  // one warp per (b, point)
    int lane = threadIdx.x & 31;
    if (gw >= BATCH * NPTS) return;

    int b = gw / NPTS;
    int p = gw - b * NPTS;
    if (contain[gw] <= 0) return;
    int cx = coors[gw * 3 + 1];
    int cy = coors[gw * 3 + 2];
    if ((unsigned)cx >= XSZ || (unsigned)cy >= YSZ) return;
    if (g_idx[(b * XSZ + cx) * YSZ + cy] != p) return;         // only the winner writes

    float px = pnts[gw * 2 + 0];
    float py = pnts[gw * 2 + 1];

    float d0 = dyn[((b * 3 + 0) * XSZ + cx) * YSZ + cy];
    float d1 = dyn[((b * 3 + 1) * XSZ + cx) * YSZ + cy];
    float d2 = dyn[((b * 3 + 2) * XSZ + cx) * YSZ + cy];

    float2 acc = make_float2(0.f, 0.f);
    sample_map<48, 160>(g_t3 + b * 48 * 160 * NCH, px, py, lane, d0, acc);
    sample_map<24,  80>(g_t4 + b * 24 *  80 * NCH, px, py, lane, d1, acc);
    sample_map<12,  40>(g_t5 + b * 12 *  40 * NCH, px, py, lane, d2, acc);

    int c = lane * 2;
    size_t o = ((size_t)(b * NCH + c) * XSZ + cx) * YSZ + cy;
    out[o]             = acc.x;
    out[o + XSZ * YSZ] = acc.y;
}

// -------- launch --------
extern "C" void kernel_launch(void* const* d_in, const int* in_sizes, int n_in,
                              void* d_out, int out_size) {
    const float* c3      = (const float*)d_in[0];
    const float* c4      = (const float*)d_in[1];
    const float* c5      = (const float*)d_in[2];
    const float* dyn     = (const float*)d_in[3];
    const float* pnts    = (const float*)d_in[4];
    const int*   coors   = (const int*)  d_in[5];
    const int*   contain = (const int*)  d_in[6];
    float*       out     = (float*)d_out;

    float *t3, *t4, *t5;
    cudaGetSymbolAddress((void**)&t3, g_t3);
    cudaGetSymbolAddress((void**)&t4, g_t4);
    cudaGetSymbolAddress((void**)&t5, g_t5);

    // 1) winner map init
    k_init_idx<<<(BATCH * XSZ * YSZ + 255) / 256, 256>>>();
    // 2) scatter point indices
    k_scatter_idx<<<(BATCH * NPTS + 255) / 256, 256>>>(coors, contain);
    // 3) transposes
    k_transpose<48, 160><<<(BATCH * 48 * 160 * NCH + 255) / 256, 256>>>(c3, t3);
    k_transpose<24,  80><<<(BATCH * 24 *  80 * NCH + 255) / 256, 256>>>(c4, t4);
    k_transpose<12,  40><<<(BATCH * 12 *  40 * NCH + 255) / 256, 256>>>(c5, t5);
    // 4) zero 256MB output
    k_zero<<<(BATCH * NCH * XSZ * YSZ / 4 + 255) / 256, 256>>>((float4*)out);
    // 5) warp-per-point sample + blend + scatter
    k_points<<<(BATCH * NPTS * 32 + 255) / 256, 256>>>(pnts, coors, contain, dyn, out);
}

// round 2
// speedup vs baseline: 1.1304x; 1.1304x over previous
#include <cuda_runtime.h>

#define BATCH 4
#define NCH   64
#define NPTS  20000
#define XSZ   512
#define YSZ   512

// feature-map pixel counts
#define P3 (48 * 160)   // 7680
#define P4 (24 * 80)    // 1920
#define P5 (12 * 40)    // 480

// -------- device scratch (allocation-free per harness rules) --------
__device__ int   g_idx[BATCH * XSZ * YSZ];      // winner point index per pixel, -1 = empty
__device__ float g_t3[BATCH * P3 * NCH];        // c3 transposed to [b][pix][c]
__device__ float g_t4[BATCH * P4 * NCH];
__device__ float g_t5[BATCH * P5 * NCH];

// -------- scatter point indices; last-update-wins == highest index wins --------
__global__ void k_scatter_idx(const int* __restrict__ coors,
                              const int* __restrict__ contain) {
    int i = blockIdx.x * blockDim.x + threadIdx.x;
    if (i >= BATCH * NPTS) return;
    if (contain[i] <= 0) return;
    int b  = i / NPTS;
    int p  = i - b * NPTS;
    int cx = coors[i * 3 + 1];
    int cy = coors[i * 3 + 2];
    if ((unsigned)cx >= XSZ || (unsigned)cy >= YSZ) return;
    atomicMax(&g_idx[(b * XSZ + cx) * YSZ + cy], p);
}

// -------- fused tiled transpose: all three maps, NCHW -> [b][pix][c] --------
// src matrix per (map, b): [C=64][P]  ->  dst [P][C=64]
// 32x32 tiles, 32x8 threads, 4 rows per thread; both directions coalesced.
#define T3_BLKS (BATCH * 2 * (P3 / 32))   // 1920
#define T4_BLKS (BATCH * 2 * (P4 / 32))   // 480
#define T5_BLKS (BATCH * 2 * (P5 / 32))   // 120
#define T_BLKS  (T3_BLKS + T4_BLKS + T5_BLKS)

__global__ void k_transpose_all(const float* __restrict__ c3,
                                const float* __restrict__ c4,
                                const float* __restrict__ c5) {
    __shared__ float s[32][33];
    int bid = blockIdx.x;
    const float* src;
    float* dst;
    int P;
    if (bid < T3_BLKS)              { src = c3; dst = g_t3; P = P3; }
    else if (bid < T3_BLKS+T4_BLKS) { bid -= T3_BLKS; src = c4; dst = g_t4; P = P4; }
    else                            { bid -= T3_BLKS + T4_BLKS; src = c5; dst = g_t5; P = P5; }

    int ptiles = P >> 5;
    int b   = bid / (2 * ptiles);
    int rem = bid - b * (2 * ptiles);
    int c0  = (rem / ptiles) << 5;
    int p0  = (rem % ptiles) << 5;
    src += (size_t)b * NCH * P;
    dst += (size_t)b * P * NCH;

    int tx = threadIdx.x, ty = threadIdx.y;
    #pragma unroll
    for (int j = 0; j < 4; j++)
        s[ty + j * 8][tx] = src[(c0 + ty + j * 8) * P + p0 + tx];
    __syncthreads();
    #pragma unroll
    for (int j = 0; j < 4; j++)
        dst[(size_t)(p0 + ty + j * 8) * NCH + c0 + tx] = s[tx][ty + j * 8];
}

// -------- warp-per-point bilinear sample + blend + scatter --------
template<int H, int W>
__device__ __forceinline__ void sample_map(const float* __restrict__ t,   // [pix][C] for this batch
                                           float px, float py, int lane,
                                           float d, float2& acc) {
    float x = px * (float)(W - 1);
    float y = py * (float)(H - 1);
    float x0f = floorf(x), y0f = floorf(y);
    float wx = x - x0f,    wy = y - y0f;
    int x0 = (int)x0f, y0 = (int)y0f;
    int x1 = x0 + 1,   y1 = y0 + 1;

    // validity (zeros padding) — matches reference exactly
    float v00 = (x0 >= 0 && x0 < W && y0 >= 0 && y0 < H) ? 1.f : 0.f;
    float v10 = (x1 >= 0 && x1 < W && y0 >= 0 && y0 < H) ? 1.f : 0.f;
    float v01 = (x0 >= 0 && x0 < W && y1 >= 0 && y1 < H) ? 1.f : 0.f;
    float v11 = (x1 >= 0 && x1 < W && y1 >= 0 && y1 < H) ? 1.f : 0.f;

    int cx0 = min(max(x0, 0), W - 1);
    int cx1 = min(max(x1, 0), W - 1);
    int cy0 = min(max(y0, 0), H - 1);
    int cy1 = min(max(y1, 0), H - 1);

    float w00 = (1.f - wx) * (1.f - wy) * v00;
    float w10 =        wx  * (1.f - wy) * v10;
    float w01 = (1.f - wx) *        wy  * v01;
    float w11 =        wx  *        wy  * v11;

    // each lane loads channels (2*lane, 2*lane+1): 32 lanes * 8B = 256B coalesced
    const float2* p00 = (const float2*)(t + (cy0 * W + cx0) * NCH) + lane;
    const float2* p10 = (const float2*)(t + (cy0 * W + cx1) * NCH) + lane;
    const float2* p01 = (const float2*)(t + (cy1 * W + cx0) * NCH) + lane;
    const float2* p11 = (const float2*)(t + (cy1 * W + cx1) * NCH) + lane;
    float2 a00 = *p00, a10 = *p10, a01 = *p01, a11 = *p11;

    acc.x += d * (w00 * a00.x + w10 * a10.x + w01 * a01.x + w11 * a11.x);
    acc.y += d * (w00 * a00.y + w10 * a10.y + w01 * a01.y + w11 * a11.y);
}

__global__ void k_points(const float* __restrict__ pnts,
                         const int*   __restrict__ coors,
                         const int*   __restrict__ contain,
                         const float* __restrict__ dyn,
                         float*       __restrict__ out) {
    int gw   = (blockIdx.x * blockDim.x + threadIdx.x) >> 5;  // one warp per (b, point)
    int lane = threadIdx.x & 31;
    if (gw >= BATCH * NPTS) return;

    int b = gw / NPTS;
    int p = gw - b * NPTS;
    if (contain[gw] <= 0) return;
    int cx = coors[gw * 3 + 1];
    int cy = coors[gw * 3 + 2];
    if ((unsigned)cx >= XSZ || (unsigned)cy >= YSZ) return;
    if (g_idx[(b * XSZ + cx) * YSZ + cy] != p) return;         // only the winner writes

    float px = pnts[gw * 2 + 0];
    float py = pnts[gw * 2 + 1];

    float d0 = dyn[((b * 3 + 0) * XSZ + cx) * YSZ + cy];
    float d1 = dyn[((b * 3 + 1) * XSZ + cx) * YSZ + cy];
    float d2 = dyn[((b * 3 + 2) * XSZ + cx) * YSZ + cy];

    float2 acc = make_float2(0.f, 0.f);
    sample_map<48, 160>(g_t3 + b * P3 * NCH, px, py, lane, d0, acc);
    sample_map<24,  80>(g_t4 + b * P4 * NCH, px, py, lane, d1, acc);
    sample_map<12,  40>(g_t5 + b * P5 * NCH, px, py, lane, d2, acc);

    int c = lane * 2;
    size_t o = ((size_t)(b * NCH + c) * XSZ + cx) * YSZ + cy;
    out[o]             = acc.x;
    out[o + XSZ * YSZ] = acc.y;
}

// -------- launch --------
extern "C" void kernel_launch(void* const* d_in, const int* in_sizes, int n_in,
                              void* d_out, int out_size) {
    const float* c3      = (const float*)d_in[0];
    const float* c4      = (const float*)d_in[1];
    const float* c5      = (const float*)d_in[2];
    const float* dyn     = (const float*)d_in[3];
    const float* pnts    = (const float*)d_in[4];
    const int*   coors   = (const int*)  d_in[5];
    const int*   contain = (const int*)  d_in[6];
    float*       out     = (float*)d_out;

    void* idx_ptr;
    cudaGetSymbolAddress(&idx_ptr, g_idx);

    // 1) init winner map: memset node, 0xFF == -1 for int32
    cudaMemsetAsync(idx_ptr, 0xFF, (size_t)BATCH * XSZ * YSZ * sizeof(int), 0);
    // 2) scatter point indices (tiny)
    k_scatter_idx<<<(BATCH * NPTS + 255) / 256, 256>>>(coors, contain);
    // 3) fused coalesced transposes
    k_transpose_all<<<T_BLKS, dim3(32, 8)>>>(c3, c4, c5);
    // 4) zero 256MB output: memset node
    cudaMemsetAsync(out, 0, (size_t)out_size * sizeof(float), 0);
    // 5) warp-per-point sample + blend + scatter
    k_points<<<(BATCH * NPTS * 32 + 255) / 256, 256>>>(pnts, coors, contain, dyn, out);
}

// round 3
// speedup vs baseline: 2.0984x; 1.8562x over previous
#include <cuda_runtime.h>

#define BATCH 4
#define NCH   64
#define NPTS  20000
#define XSZ   512
#define YSZ   512
#define YTILE 128
#define NYT   (YSZ / YTILE)   // 4

// feature-map pixel counts
#define P3 (48 * 160)   // 7680
#define P4 (24 * 80)    // 1920
#define P5 (12 * 40)    // 480

// -------- device scratch (allocation-free per harness rules) --------
__device__ int   g_idx[BATCH * XSZ * YSZ];      // winner point index per pixel, -1 = empty
__device__ float g_t3[BATCH * P3 * NCH];        // features transposed to [b][pix][c]
__device__ float g_t4[BATCH * P4 * NCH];
__device__ float g_t5[BATCH * P5 * NCH];

// -------- scatter point indices; last-update-wins == highest index wins --------
__global__ void k_scatter_idx(const int* __restrict__ coors,
                              const int* __restrict__ contain) {
    int i = blockIdx.x * blockDim.x + threadIdx.x;
    if (i >= BATCH * NPTS) return;
    if (contain[i] <= 0) return;
    int b  = i / NPTS;
    int p  = i - b * NPTS;
    int cx = coors[i * 3 + 1];
    int cy = coors[i * 3 + 2];
    if ((unsigned)cx >= XSZ || (unsigned)cy >= YSZ) return;
    atomicMax(&g_idx[(b * XSZ + cx) * YSZ + cy], p);
}

// -------- fused tiled transpose: all three maps, NCHW -> [b][pix][c] --------
#define T3_BLKS (BATCH * 2 * (P3 / 32))   // 1920
#define T4_BLKS (BATCH * 2 * (P4 / 32))   // 480
#define T5_BLKS (BATCH * 2 * (P5 / 32))   // 120
#define T_BLKS  (T3_BLKS + T4_BLKS + T5_BLKS)

__global__ void k_transpose_all(const float* __restrict__ c3,
                                const float* __restrict__ c4,
                                const float* __restrict__ c5) {
    __shared__ float s[32][33];
    int bid = blockIdx.x;
    const float* src;
    float* dst;
    int P;
    if (bid < T3_BLKS)              { src = c3; dst = g_t3; P = P3; }
    else if (bid < T3_BLKS+T4_BLKS) { bid -= T3_BLKS; src = c4; dst = g_t4; P = P4; }
    else                            { bid -= T3_BLKS + T4_BLKS; src = c5; dst = g_t5; P = P5; }

    int ptiles = P >> 5;
    int b   = bid / (2 * ptiles);
    int rem = bid - b * (2 * ptiles);
    int c0  = (rem / ptiles) << 5;
    int p0  = (rem % ptiles) << 5;
    src += (size_t)b * NCH * P;
    dst += (size_t)b * P * NCH;

    int tx = threadIdx.x, ty = threadIdx.y;
    #pragma unroll
    for (int j = 0; j < 4; j++)
        s[ty + j * 8][tx] = src[(c0 + ty + j * 8) * P + p0 + tx];
    __syncthreads();
    #pragma unroll
    for (int j = 0; j < 4; j++)
        dst[(size_t)(p0 + ty + j * 8) * NCH + c0 + tx] = s[tx][ty + j * 8];
}

// -------- bilinear sample of one transposed map, warp-wide over channels --------
template<int H, int W>
__device__ __forceinline__ void sample_map(const float* __restrict__ t,   // [pix][C] for this batch
                                           float px, float py, int lane,
                                           float d, float2& acc) {
    float x = px * (float)(W - 1);
    float y = py * (float)(H - 1);
    float x0f = floorf(x), y0f = floorf(y);
    float wx = x - x0f,    wy = y - y0f;
    int x0 = (int)x0f, y0 = (int)y0f;
    int x1 = x0 + 1,   y1 = y0 + 1;

    float v00 = (x0 >= 0 && x0 < W && y0 >= 0 && y0 < H) ? 1.f : 0.f;
    float v10 = (x1 >= 0 && x1 < W && y0 >= 0 && y0 < H) ? 1.f : 0.f;
    float v01 = (x0 >= 0 && x0 < W && y1 >= 0 && y1 < H) ? 1.f : 0.f;
    float v11 = (x1 >= 0 && x1 < W && y1 >= 0 && y1 < H) ? 1.f : 0.f;

    int cx0 = min(max(x0, 0), W - 1);
    int cx1 = min(max(x1, 0), W - 1);
    int cy0 = min(max(y0, 0), H - 1);
    int cy1 = min(max(y1, 0), H - 1);

    float w00 = (1.f - wx) * (1.f - wy) * v00;
    float w10 =        wx  * (1.f - wy) * v10;
    float w01 = (1.f - wx) *        wy  * v01;
    float w11 =        wx  *        wy  * v11;

    const float2* p00 = (const float2*)(t + (cy0 * W + cx0) * NCH) + lane;
    const float2* p10 = (const float2*)(t + (cy0 * W + cx1) * NCH) + lane;
    const float2* p01 = (const float2*)(t + (cy1 * W + cx0) * NCH) + lane;
    const float2* p11 = (const float2*)(t + (cy1 * W + cx1) * NCH) + lane;
    float2 a00 = *p00, a10 = *p10, a01 = *p01, a11 = *p11;

    acc.x += d * (w00 * a00.x + w10 * a10.x + w01 * a01.x + w11 * a11.x);
    acc.y += d * (w00 * a00.y + w10 * a10.y + w01 * a01.y + w11 * a11.y);
}

// -------- fused: zero-fill + sample + blend, streaming the output once --------
// One block per (b, x, ytile). 256 threads = 8 warps. smem tile [128 y][64 ch].
__global__ __launch_bounds__(256) void k_fused(const float* __restrict__ pnts,
                                               const float* __restrict__ dyn,
                                               float*       __restrict__ out) {
    __shared__ float sm[YTILE][NCH + 1];   // +1 pad: conflict-free both phases
    __shared__ int   list[YTILE];
    __shared__ int   cnt;

    int blk   = blockIdx.x;
    int b     = blk / (XSZ * NYT);
    int rem   = blk - b * (XSZ * NYT);
    int x     = rem / NYT;
    int y0    = (rem - x * NYT) * YTILE;

    int tid  = threadIdx.x;
    int lane = tid & 31;
    int wid  = tid >> 5;

    if (tid == 0) cnt = 0;
    // zero the smem tile
    for (int i = tid; i < YTILE * (NCH + 1); i += 256)
        ((float*)sm)[i] = 0.f;
    __syncthreads();

    // gather active pixels of this column tile
    if (tid < YTILE) {
        int p = g_idx[(b * XSZ + x) * YSZ + y0 + tid];
        if (p >= 0) {
            int slot = atomicAdd(&cnt, 1);
            list[slot] = (tid << 15) | p;      // p < 20000 < 2^15
        }
    }
    __syncthreads();

    // warp-per-active-pixel sampling
    int nact = cnt;
    for (int k = wid; k < nact; k += 8) {
        int e    = list[k];
        int yloc = e >> 15;
        int p    = e & 0x7FFF;
        int cy   = y0 + yloc;

        float px = pnts[(b * NPTS + p) * 2 + 0];
        float py = pnts[(b * NPTS + p) * 2 + 1];
        float d0 = dyn[((b * 3 + 0) * XSZ + x) * YSZ + cy];
        float d1 = dyn[((b * 3 + 1) * XSZ + x) * YSZ + cy];
        float d2 = dyn[((b * 3 + 2) * XSZ + x) * YSZ + cy];

        float2 acc = make_float2(0.f, 0.f);
        sample_map<48, 160>(g_t3 + b * P3 * NCH, px, py, lane, d0, acc);
        sample_map<24,  80>(g_t4 + b * P4 * NCH, px, py, lane, d1, acc);
        sample_map<12,  40>(g_t5 + b * P5 * NCH, px, py, lane, d2, acc);

        sm[yloc][2 * lane]     = acc.x;
        sm[yloc][2 * lane + 1] = acc.y;
    }
    __syncthreads();

    // stream the tile out: fully coalesced, one pass over the output
    size_t base = ((size_t)b * NCH * XSZ + x) * YSZ + y0;
    for (int i = tid; i < NCH * YTILE; i += 256) {
        int c = i >> 7;          // channel
        int y = i & (YTILE - 1); // y within tile
        out[base + (size_t)c * (XSZ * YSZ) + y] = sm[y][c];
    }
}

// -------- launch --------
extern "C" void kernel_launch(void* const* d_in, const int* in_sizes, int n_in,
                              void* d_out, int out_size) {
    const float* c3      = (const float*)d_in[0];
    const float* c4      = (const float*)d_in[1];
    const float* c5      = (const float*)d_in[2];
    const float* dyn     = (const float*)d_in[3];
    const float* pnts    = (const float*)d_in[4];
    const int*   coors   = (const int*)  d_in[5];
    const int*   contain = (const int*)  d_in[6];
    float*       out     = (float*)d_out;

    void* idx_ptr;
    cudaGetSymbolAddress(&idx_ptr, g_idx);

    // 1) init winner map: memset node, 0xFF == -1 for int32
    cudaMemsetAsync(idx_ptr, 0xFF, (size_t)BATCH * XSZ * YSZ * sizeof(int), 0);
    // 2) scatter point indices
    k_scatter_idx<<<(BATCH * NPTS + 255) / 256, 256>>>(coors, contain);
    // 3) fused coalesced transposes
    k_transpose_all<<<T_BLKS, dim3(32, 8)>>>(c3, c4, c5);
    // 4) fused zero + sample + blend + coalesced output stream
    k_fused<<<BATCH * XSZ * NYT, 256>>>(pnts, dyn, out);
}